// round 12
// baseline (speedup 1.0000x reference)
#include <cuda_runtime.h>
#include <cstdint>

typedef unsigned long long u64;

// ---------------------------------------------------------------------------
// Dimensions
// x: (16,2,128,128,64) -> conv1 (8,2,5,5) s4 p1 -> (16,8,32,32,T)
// -> conv2 (32,8,5,5) -> (16,32,8,8,T) -> conv3 (64,32,5,5) -> (16,64,2,2,T)
// -> dense1 256->2056 -> dense2 2056->11 -> out (16,11,64)
// ---------------------------------------------------------------------------

// float pool offsets
#define W1_OFF   0              // 8*50
#define W2_OFF   400            // 32*200
#define W3_OFF   6800           // 64*800
#define W4T_OFF  58000          // 256 * 2304 (transposed, padded rows)
#define W5_OFF   647824         // 11*2056
#define Z3P_OFF  670440         // 16*4*256*64 = 1048576 (conv3 partial z)
#define FBUF_TOTAL 1719016

#define W4T_STRIDE 2304

// u64 pool offsets
#define XP_OFF 0                // 16*2*128*128
#define S1_OFF 524288           // 16*8*32*32
#define S2_OFF 655360           // 16*32*8*8
#define S3_OFF 688128           // 16*256
#define S4_OFF 692224           // 16*2056
#define UBUF_TOTAL 725120

__device__ float g_fbuf[FBUF_TOTAL];
__device__ u64   g_ubuf[UBUF_TOTAL];

// ---------------------------------------------------------------------------
// f32x2 packed-FMA helpers (two exact IEEE fp32 lanes -> bit-identical z)
// ---------------------------------------------------------------------------
__device__ __forceinline__ void ffma2(u64& d, u64 a, u64 b)
{
    asm("fma.rn.f32x2 %0, %1, %2, %0;" : "+l"(d) : "l"(a), "l"(b));
}
#define ONE2 0x3F8000003F800000ULL
__device__ __forceinline__ u64 bit2f2(unsigned int word, int t)
{
    return ((word >> t) & 1u) ? ONE2 : 0ULL;
}
__device__ __forceinline__ void unpack2(u64 p, float& lo, float& hi)
{
    unsigned int l_, h_;
    asm("mov.b64 {%0,%1}, %2;" : "=r"(l_), "=r"(h_) : "l"(p));
    lo = __uint_as_float(l_);
    hi = __uint_as_float(h_);
}

// ---------------------------------------------------------------------------
// Merged init kernel: blocks [0,2048) pack input spikes; blocks [2048,4219)
// run weight_norm for all 5 layers (dense1 transposed, padded rows).
// ---------------------------------------------------------------------------
__global__ void __launch_bounds__(256)
init_kernel(const float* __restrict__ x, u64* __restrict__ xp,
            const float* __restrict__ c1v, const float* __restrict__ c1g,
            const float* __restrict__ c2v, const float* __restrict__ c2g,
            const float* __restrict__ c3v, const float* __restrict__ c3g,
            const float* __restrict__ d1v, const float* __restrict__ d1g,
            const float* __restrict__ d2v, const float* __restrict__ d2g)
{
    __shared__ unsigned int nsm[256 * 17];
    const int tid = threadIdx.x;

    if (blockIdx.x < 2048) {
        const float4* xg = (const float4*)x + (size_t)blockIdx.x * 4096;
        #pragma unroll
        for (int j = 0; j < 16; ++j) {
            float4 f = xg[j * 256 + tid];
            unsigned int v = (f.x > 0.5f ? 1u : 0u) | (f.y > 0.5f ? 2u : 0u)
                           | (f.z > 0.5f ? 4u : 0u) | (f.w > 0.5f ? 8u : 0u);
            int pl  = j * 16 + (tid >> 4);
            int nib = tid & 15;
            nsm[pl * 17 + nib] = v;
        }
        __syncthreads();
        u64 m = 0;
        #pragma unroll
        for (int k = 0; k < 16; ++k)
            m |= (u64)nsm[tid * 17 + k] << (4 * k);
        xp[(size_t)blockIdx.x * 256 + tid] = m;
        return;
    }

    int blk = blockIdx.x - 2048;
    const float* v; const float* g; float* w; int cols; int r; int trans = 0;
    if (blk < 8)          { v = c1v; g = c1g; w = g_fbuf + W1_OFF;  cols = 50;   r = blk; }
    else if (blk < 40)    { v = c2v; g = c2g; w = g_fbuf + W2_OFF;  cols = 200;  r = blk - 8; }
    else if (blk < 104)   { v = c3v; g = c3g; w = g_fbuf + W3_OFF;  cols = 800;  r = blk - 40; }
    else if (blk < 2160)  { v = d1v; g = d1g; w = g_fbuf + W4T_OFF; cols = 256;  r = blk - 104; trans = 1; }
    else                  { v = d2v; g = d2g; w = g_fbuf + W5_OFF;  cols = 2056; r = blk - 2160; }

    float* red = (float*)nsm;
    float s = 0.0f;
    for (int i = tid; i < cols; i += 256) {
        float a = v[(size_t)r * cols + i];
        s += a * a;
    }
    red[tid] = s;
    __syncthreads();
    for (int off = 128; off > 0; off >>= 1) {
        if (tid < off) red[tid] += red[tid + off];
        __syncthreads();
    }
    float n = sqrtf(red[0]);
    float gr = g[r];
    if (!trans) {
        for (int i = tid; i < cols; i += 256)
            w[(size_t)r * cols + i] = gr * v[(size_t)r * cols + i] / n;
    } else {
        for (int i = tid; i < cols; i += 256)
            w[(size_t)i * W4T_STRIDE + r] = gr * v[(size_t)r * cols + i] / n;
    }
}

// ---------------------------------------------------------------------------
// conv1: 2->8, in 128x128, out 32x32. Grid (16 b, 32 y, 2 xh) = 1024 blocks.
// 256 thr = 16 tq x 16 px; thread tile 8o x 4t = 16 FFMA2 per word.
// ---------------------------------------------------------------------------
__global__ void __launch_bounds__(256, 3)
conv1_kernel(const u64* __restrict__ xp, const float* __restrict__ wn,
             u64* __restrict__ sp)
{
    __shared__ u64 tile[2][5][65];                 // zero-padded halo
    __shared__ __align__(16) float wsm[400];       // [50 taps][8 o]
    __shared__ float zsm[128 * 65];                // 128 neurons

    const int b = blockIdx.x, y = blockIdx.y, xh = blockIdx.z;
    const int tid = threadIdx.x;
    const int tq = tid & 15, pxl = tid >> 4;

    for (int idx = tid; idx < 400; idx += 256)
        wsm[idx] = wn[(idx & 7) * 50 + (idx >> 3)];
    for (int idx = tid; idx < 650; idx += 256) {
        int c = idx / 325, rem = idx % 325;
        int r = rem / 65, col = rem % 65;
        int gy = 4 * y - 1 + r;
        int gx = xh * 64 - 1 + col;
        u64 v = 0ULL;
        if (gy >= 0 && gx >= 0)
            v = xp[(((size_t)b * 2 + c) << 14) + ((size_t)gy << 7) + gx];
        tile[c][r][col] = v;
    }
    __syncthreads();

    u64 acc[4][4];   // [opair][k(t)]
    #pragma unroll
    for (int j = 0; j < 4; ++j)
        #pragma unroll
        for (int k = 0; k < 4; ++k) acc[j][k] = 0ULL;

    #pragma unroll
    for (int c = 0; c < 2; ++c) {
        #pragma unroll 1
        for (int ky = 0; ky < 5; ++ky) {
            #pragma unroll
            for (int kx = 0; kx < 5; ++kx) {
                u64 word = tile[c][ky][pxl * 4 + kx];
                unsigned int lo = (unsigned int)word;
                unsigned int hi = (unsigned int)(word >> 32);
                u64 fd[4];
                fd[0] = bit2f2(lo, tq);
                fd[1] = bit2f2(lo, tq + 16);
                fd[2] = bit2f2(hi, tq);
                fd[3] = bit2f2(hi, tq + 16);
                const ulonglong2* wp =
                    (const ulonglong2*)(wsm + (c * 25 + ky * 5 + kx) * 8);
                ulonglong2 wA = wp[0];
                ulonglong2 wB = wp[1];
                u64 wpair[4] = {wA.x, wA.y, wB.x, wB.y};
                #pragma unroll
                for (int k = 0; k < 4; ++k)
                    #pragma unroll
                    for (int j = 0; j < 4; ++j)
                        ffma2(acc[j][k], wpair[j], fd[k]);
            }
        }
    }

    #pragma unroll
    for (int j = 0; j < 4; ++j)
        #pragma unroll
        for (int k = 0; k < 4; ++k) {
            float lo, hi;
            unpack2(acc[j][k], lo, hi);
            zsm[((2 * j)     * 16 + pxl) * 65 + tq + 16 * k] = lo;
            zsm[((2 * j + 1) * 16 + pxl) * 65 + tq + 16 * k] = hi;
        }
    __syncthreads();

    if (tid < 128) {   // CUBA: neuron = (o, pxl)
        int o = tid >> 4, p = tid & 15;
        float cc = 0.0f, vv = 0.0f;
        u64 m = 0;
        #pragma unroll 1
        for (int tt = 0; tt < 64; ++tt) {
            float z = zsm[tid * 65 + tt];
            cc = 0.7f * cc + z;
            vv = 0.75f * vv + cc;
            if (vv >= 1.0f) { m |= (1ULL << tt); vv = 0.0f; }
        }
        sp[(((size_t)b * 8 + o) * 32 + y) * 32 + xh * 16 + p] = m;
    }
}

// ---------------------------------------------------------------------------
// conv2: 8->32, in 32x32, out 8x8. Grid (16 b, 8 yq, 8 og of 4o) = 1024
// blocks x 128 thr. 16 tq x 8 px; thread tile 4o x 4t = 8 FFMA2 per word.
// ---------------------------------------------------------------------------
__global__ void __launch_bounds__(128, 7)
conv2_kernel(const u64* __restrict__ s1, const float* __restrict__ wn,
             u64* __restrict__ sp)
{
    __shared__ u64 tile[8][5][33];                 // zero-padded halo
    __shared__ __align__(16) float wsm[800];       // [200 taps][4 o]
    __shared__ float zsm[32 * 65];                 // 32 neurons

    const int b = blockIdx.x, yq = blockIdx.y, og = blockIdx.z;
    const int tid = threadIdx.x;
    const int tq = tid & 15, px = tid >> 4;        // px = output x, 0..7

    for (int idx = tid; idx < 800; idx += 128)
        wsm[idx] = wn[(og * 4 + (idx & 3)) * 200 + (idx >> 2)];
    for (int idx = tid; idx < 1320; idx += 128) {
        int c = idx / 165, rem = idx % 165;
        int r = rem / 33, col = rem % 33;
        int gy = 4 * yq - 1 + r;
        int gx = col - 1;
        u64 v = 0ULL;
        if (gy >= 0 && gx >= 0)
            v = s1[(((size_t)b * 8 + c) << 10) + ((size_t)gy << 5) + gx];
        tile[c][r][col] = v;
    }
    __syncthreads();

    u64 acc[2][4];   // [opair][k(t)]
    #pragma unroll
    for (int j = 0; j < 2; ++j)
        #pragma unroll
        for (int k = 0; k < 4; ++k) acc[j][k] = 0ULL;

    #pragma unroll 1
    for (int c = 0; c < 8; ++c) {
        #pragma unroll 1
        for (int ky = 0; ky < 5; ++ky) {
            #pragma unroll
            for (int kx = 0; kx < 5; ++kx) {
                u64 word = tile[c][ky][px * 4 + kx];
                unsigned int lo = (unsigned int)word;
                unsigned int hi = (unsigned int)(word >> 32);
                u64 fd[4];
                fd[0] = bit2f2(lo, tq);
                fd[1] = bit2f2(lo, tq + 16);
                fd[2] = bit2f2(hi, tq);
                fd[3] = bit2f2(hi, tq + 16);
                ulonglong2 wA =
                    *(const ulonglong2*)(wsm + (c * 25 + ky * 5 + kx) * 4);
                #pragma unroll
                for (int k = 0; k < 4; ++k) {
                    ffma2(acc[0][k], wA.x, fd[k]);
                    ffma2(acc[1][k], wA.y, fd[k]);
                }
            }
        }
    }

    #pragma unroll
    for (int j = 0; j < 2; ++j)
        #pragma unroll
        for (int k = 0; k < 4; ++k) {
            float lo, hi;
            unpack2(acc[j][k], lo, hi);
            zsm[((2 * j)     * 8 + px) * 65 + tq + 16 * k] = lo;
            zsm[((2 * j + 1) * 8 + px) * 65 + tq + 16 * k] = hi;
        }
    __syncthreads();

    if (tid < 32) {   // CUBA: neuron = (o_local, px)
        int o_loc = tid >> 3, p = tid & 7;
        float cc = 0.0f, vv = 0.0f;
        u64 m = 0;
        #pragma unroll 1
        for (int tt = 0; tt < 64; ++tt) {
            float z = zsm[tid * 65 + tt];
            cc = 0.7f * cc + z;
            vv = 0.75f * vv + cc;
            if (vv >= 1.0f) { m |= (1ULL << tt); vv = 0.0f; }
        }
        sp[(((size_t)b * 32 + og * 4 + o_loc) * 8 + yq) * 8 + p] = m;
    }
}

// ---------------------------------------------------------------------------
// conv3 partial: 8 channels per block. Grid (16 b, 8 og, 4 csub) = 512
// blocks x 256 thr (64t x 4pos). Zero-padded u32 tile, branch-free inner
// loop (LDS32 + extract + 2xLDS128 + 4 FFMA2 per word). Partial z staged
// in smem, written coalesced to global scratch [b][csub][neuron][t].
// ---------------------------------------------------------------------------
__global__ void __launch_bounds__(256, 4)
conv3_partial_kernel(const u64* __restrict__ s2, const float* __restrict__ wn,
                     float* __restrict__ zp)
{
    __shared__ unsigned int tile32[8 * 81 * 2];        // 5184 B, zero-padded
    __shared__ __align__(16) float wsm[1600];          // [8c*25 taps][8 o]
    __shared__ float zs[32 * 65];                      // 32 neurons staged

    const int b = blockIdx.x, og = blockIdx.y, csub = blockIdx.z;
    const int tid = threadIdx.x;
    const int t = tid & 63, pq = tid >> 6;
    const int y = pq >> 1, x = pq & 1;
    const int hiofs = (t >= 32) ? 1 : 0;
    const int tb = t & 31;

    // weights: wsm[(cl*25+tap)*8 + o] for global c = csub*8+cl
    for (int idx = tid; idx < 1600; idx += 256) {
        int o = idx & 7, tapcl = idx >> 3;
        wsm[idx] = wn[(og * 8 + o) * 800 + csub * 200 + tapcl];
    }
    // input tile for 8 channels, zero-padded [8][9][9] x (lo,hi)
    for (int idx = tid; idx < 648; idx += 256) {
        int cl = idx / 81, rem = idx % 81;
        int r = rem / 9, col = rem % 9;
        u64 v = 0ULL;
        if (r >= 1 && col >= 1)
            v = s2[(size_t)b * 2048 + (csub * 8 + cl) * 64 + (r - 1) * 8 + (col - 1)];
        tile32[idx * 2]     = (unsigned int)v;
        tile32[idx * 2 + 1] = (unsigned int)(v >> 32);
    }
    __syncthreads();

    u64 acc[4] = {0ULL, 0ULL, 0ULL, 0ULL};

    #pragma unroll 1
    for (int cl = 0; cl < 8; ++cl) {
        #pragma unroll 1
        for (int ky = 0; ky < 5; ++ky) {
            const unsigned int* row =
                tile32 + (cl * 81 + (4 * y + ky) * 9 + 4 * x) * 2 + hiofs;
            const float* wrow = wsm + (cl * 25 + ky * 5) * 8;
            #pragma unroll
            for (int kx = 0; kx < 5; ++kx) {
                unsigned int half = row[kx * 2];
                u64 f = bit2f2(half, tb);
                const ulonglong2* wp = (const ulonglong2*)(wrow + kx * 8);
                ulonglong2 w01 = wp[0];
                ulonglong2 w23 = wp[1];
                ffma2(acc[0], w01.x, f);
                ffma2(acc[1], w01.y, f);
                ffma2(acc[2], w23.x, f);
                ffma2(acc[3], w23.y, f);
            }
        }
    }

    #pragma unroll
    for (int j = 0; j < 4; ++j) {
        float lo, hi;
        unpack2(acc[j], lo, hi);
        zs[((2 * j)     * 4 + pq) * 65 + t] = lo;
        zs[((2 * j + 1) * 4 + pq) * 65 + t] = hi;
    }
    __syncthreads();

    // coalesced write: zp[((b*4+csub)*256 + og*32 + n)*64 + tt]
    float* dst = zp + (((size_t)b * 4 + csub) * 256 + og * 32) * 64;
    for (int idx = tid; idx < 2048; idx += 256) {
        int n = idx >> 6, tt = idx & 63;
        dst[n * 64 + tt] = zs[n * 65 + tt];
    }
}

// ---------------------------------------------------------------------------
// conv3 reduce + CUBA: grid 16, 256 thr (one per neuron). float4 loads of
// the 4 partials; reduction order ((p0+p1)+p2)+p3 matches prior kernel.
// ---------------------------------------------------------------------------
__global__ void __launch_bounds__(256)
conv3_reduce_kernel(const float* __restrict__ zp, u64* __restrict__ s3)
{
    const int b = blockIdx.x, n = threadIdx.x;
    const float* p0 = zp + (((size_t)b * 4 + 0) * 256 + n) * 64;
    const float* p1 = zp + (((size_t)b * 4 + 1) * 256 + n) * 64;
    const float* p2 = zp + (((size_t)b * 4 + 2) * 256 + n) * 64;
    const float* p3 = zp + (((size_t)b * 4 + 3) * 256 + n) * 64;

    float cc = 0.0f, vv = 0.0f;
    u64 m = 0;
    #pragma unroll 1
    for (int tt = 0; tt < 64; tt += 4) {
        float4 z0 = *(const float4*)(p0 + tt);
        float4 z1 = *(const float4*)(p1 + tt);
        float4 z2 = *(const float4*)(p2 + tt);
        float4 z3 = *(const float4*)(p3 + tt);
        float zz[4];
        zz[0] = ((z0.x + z1.x) + z2.x) + z3.x;
        zz[1] = ((z0.y + z1.y) + z2.y) + z3.y;
        zz[2] = ((z0.z + z1.z) + z2.z) + z3.z;
        zz[3] = ((z0.w + z1.w) + z2.w) + z3.w;
        #pragma unroll
        for (int k = 0; k < 4; ++k) {
            cc = 0.7f * cc + zz[k];
            vv = 0.75f * vv + cc;
            if (vv >= 1.0f) { m |= (1ULL << (tt + k)); vv = 0.0f; }
        }
    }
    s3[b * 256 + n] = m;
}

// ---------------------------------------------------------------------------
// dense1: 256->2056 + CUBA. Grid (16 b, 33 og of 64 o) = 528 blocks x 256
// thr: 32 tq x 8 oq; thread tile 8o (4 pairs) x 2t = 8 FFMA2 per word.
// Block-uniform zero-word skip.
// ---------------------------------------------------------------------------
__global__ void __launch_bounds__(256, 5)
dense1_cuba_kernel(const u64* __restrict__ s3,
                   const float* __restrict__ w4t,
                   u64* __restrict__ s4)
{
    __shared__ u64 words[256];
    __shared__ __align__(16) float wsm[64 * 64];   // [i][64 o]
    __shared__ float zsm[64 * 65];

    const int b = blockIdx.x, og = blockIdx.y;
    const int tid = threadIdx.x;
    const int tq = tid & 31, oq = tid >> 5;        // oq 0..7, 8 o each

    words[tid] = s3[b * 256 + tid];

    u64 acc[4][2];
    #pragma unroll
    for (int j = 0; j < 4; ++j) { acc[j][0] = 0ULL; acc[j][1] = 0ULL; }

    #pragma unroll 1
    for (int q = 0; q < 4; ++q) {
        __syncthreads();
        #pragma unroll
        for (int r = 0; r < 4; ++r) {
            int f4 = r * 256 + tid;
            int ii = f4 >> 4;
            int o4 = (f4 & 15) * 4;
            *(float4*)(wsm + ii * 64 + o4) =
                *(const float4*)(w4t + (size_t)(q * 64 + ii) * W4T_STRIDE + og * 64 + o4);
        }
        __syncthreads();

        #pragma unroll 2
        for (int ii = 0; ii < 64; ++ii) {
            u64 wd = words[q * 64 + ii];
            if (wd == 0ULL) continue;          // block-uniform, exact skip
            u64 f0 = bit2f2((unsigned int)wd, tq);
            u64 f1 = bit2f2((unsigned int)(wd >> 32), tq);
            const ulonglong2* wp = (const ulonglong2*)(wsm + ii * 64 + oq * 8);
            ulonglong2 w0 = wp[0], w1 = wp[1];
            u64 wpair[4] = {w0.x, w0.y, w1.x, w1.y};
            #pragma unroll
            for (int j = 0; j < 4; ++j) {
                ffma2(acc[j][0], wpair[j], f0);
                ffma2(acc[j][1], wpair[j], f1);
            }
        }
    }

    #pragma unroll
    for (int j = 0; j < 4; ++j)
        #pragma unroll
        for (int k = 0; k < 2; ++k) {
            float lo, hi;
            unpack2(acc[j][k], lo, hi);
            zsm[(oq * 8 + 2 * j)     * 65 + tq + 32 * k] = lo;
            zsm[(oq * 8 + 2 * j + 1) * 65 + tq + 32 * k] = hi;
        }
    __syncthreads();

    if (tid < 64) {
        int o_g = og * 64 + tid;
        float cc = 0.0f, vv = 0.0f;
        u64 m = 0;
        #pragma unroll 1
        for (int tt = 0; tt < 64; ++tt) {
            float z = zsm[tid * 65 + tt];
            cc = 0.7f * cc + z;
            vv = 0.75f * vv + cc;
            if (vv >= 1.0f) { m |= (1ULL << tt); vv = 0.0f; }
        }
        if (o_g < 2056) s4[b * 2056 + o_g] = m;
    }
}

// ---------------------------------------------------------------------------
// dense2 (2056->11) + final CUBA + float output. Grid (16 b, 11 o).
// ---------------------------------------------------------------------------
__global__ void __launch_bounds__(256)
dense2_out_kernel(const u64* __restrict__ s4, const float* __restrict__ w5,
                  float* __restrict__ out)
{
    __shared__ float part[4][64];
    __shared__ float zrow[64];
    __shared__ u64 spk;

    const int b = blockIdx.x, o = blockIdx.y;
    const int tid = threadIdx.x;
    const int t = tid & 63, q = tid >> 6;

    float s = 0.0f;
    const u64*   wp = s4 + b * 2056;
    const float* vp = w5 + (size_t)o * 2056;
    for (int i = q * 514; i < q * 514 + 514; ++i) {
        float wt = vp[i];
        if ((wp[i] >> t) & 1ULL) s += wt;
    }
    part[q][t] = s;
    __syncthreads();
    if (tid < 64)
        zrow[tid] = part[0][tid] + part[1][tid] + part[2][tid] + part[3][tid];
    __syncthreads();
    if (tid == 0) {
        float cc = 0.0f, vv = 0.0f;
        u64 m = 0;
        #pragma unroll 1
        for (int tt = 0; tt < 64; ++tt) {
            cc = 0.7f * cc + zrow[tt];
            vv = 0.75f * vv + cc;
            if (vv >= 1.0f) { m |= (1ULL << tt); vv = 0.0f; }
        }
        spk = m;
    }
    __syncthreads();
    if (tid < 64)
        out[((size_t)b * 11 + o) * 64 + tid] = (float)((spk >> tid) & 1ULL);
}

// ---------------------------------------------------------------------------
// launch
// ---------------------------------------------------------------------------
extern "C" void kernel_launch(void* const* d_in, const int* in_sizes, int n_in,
                              void* d_out, int out_size)
{
    const float* x   = (const float*)d_in[0];
    const float* c1v = (const float*)d_in[1];
    const float* c1g = (const float*)d_in[2];
    const float* c2v = (const float*)d_in[3];
    const float* c2g = (const float*)d_in[4];
    const float* c3v = (const float*)d_in[5];
    const float* c3g = (const float*)d_in[6];
    const float* d1v = (const float*)d_in[7];
    const float* d1g = (const float*)d_in[8];
    const float* d2v = (const float*)d_in[9];
    const float* d2g = (const float*)d_in[10];
    float* out = (float*)d_out;

    void* fp = nullptr; void* up = nullptr;
    cudaGetSymbolAddress(&fp, g_fbuf);
    cudaGetSymbolAddress(&up, g_ubuf);
    float* F = (float*)fp;
    u64*   U = (u64*)up;

    float* W1  = F + W1_OFF;
    float* W2  = F + W2_OFF;
    float* W3  = F + W3_OFF;
    float* W4T = F + W4T_OFF;
    float* W5  = F + W5_OFF;
    float* Z3P = F + Z3P_OFF;
    u64* XP = U + XP_OFF;  u64* S1 = U + S1_OFF;  u64* S2 = U + S2_OFF;
    u64* S3 = U + S3_OFF;  u64* S4 = U + S4_OFF;

    init_kernel<<<4219, 256>>>(x, XP, c1v, c1g, c2v, c2g, c3v, c3g,
                               d1v, d1g, d2v, d2g);

    conv1_kernel<<<dim3(16, 32, 2), 256>>>(XP, W1, S1);
    conv2_kernel<<<dim3(16, 8, 8), 128>>>(S1, W2, S2);
    conv3_partial_kernel<<<dim3(16, 8, 4), 256>>>(S2, W3, Z3P);
    conv3_reduce_kernel<<<16, 256>>>(Z3P, S3);

    dense1_cuba_kernel<<<dim3(16, 33), 256>>>(S3, W4T, S4);
    dense2_out_kernel<<<dim3(16, 11), 256>>>(S4, W5, out);
}

// round 13
// speedup vs baseline: 1.0691x; 1.0691x over previous
#include <cuda_runtime.h>
#include <cstdint>

typedef unsigned long long u64;

// ---------------------------------------------------------------------------
// Dimensions
// x: (16,2,128,128,64) -> conv1 (8,2,5,5) s4 p1 -> (16,8,32,32,T)
// -> conv2 (32,8,5,5) -> (16,32,8,8,T) -> conv3 (64,32,5,5) -> (16,64,2,2,T)
// -> dense1 256->2056 -> dense2 2056->11 -> out (16,11,64)
// ---------------------------------------------------------------------------

// float pool offsets
#define W1_OFF   0              // 8*50
#define W2_OFF   400            // 32*200
#define W3_OFF   6800           // 64*800
#define W4T_OFF  58000          // 256 * 2304 (transposed, padded rows)
#define W5_OFF   647824         // 11*2056
#define NRM1_OFF 670440         // 2056 dense1 norms ||v||
#define FBUF_TOTAL 672496

#define W4T_STRIDE 2304

// u64 pool offsets
#define XP_OFF 0                // 16*2*128*128
#define S1_OFF 524288           // 16*8*32*32
#define S2_OFF 655360           // 16*32*8*8
#define S3_OFF 688128           // 16*256
#define S4_OFF 692224           // 16*2056
#define UBUF_TOTAL 725120

__device__ float g_fbuf[FBUF_TOTAL];
__device__ u64   g_ubuf[UBUF_TOTAL];

// ---------------------------------------------------------------------------
// f32x2 packed-FMA helpers (two exact IEEE fp32 lanes -> bit-identical z)
// ---------------------------------------------------------------------------
__device__ __forceinline__ void ffma2(u64& d, u64 a, u64 b)
{
    asm("fma.rn.f32x2 %0, %1, %2, %0;" : "+l"(d) : "l"(a), "l"(b));
}
#define ONE2 0x3F8000003F800000ULL
__device__ __forceinline__ u64 bit2f2(unsigned int word, int t)
{
    return ((word >> t) & 1u) ? ONE2 : 0ULL;
}
__device__ __forceinline__ void unpack2(u64 p, float& lo, float& hi)
{
    unsigned int l_, h_;
    asm("mov.b64 {%0,%1}, %2;" : "=r"(l_), "=r"(h_) : "l"(p));
    lo = __uint_as_float(l_);
    hi = __uint_as_float(h_);
}

// ---------------------------------------------------------------------------
// Merged init kernel: blocks [0,2048) pack input spikes; blocks [2048,4219)
// run weight_norm. dense1 blocks compute ONLY ||v|| per row (the transposed
// write is done coalesced by d1trans_kernel).
// ---------------------------------------------------------------------------
__global__ void __launch_bounds__(256)
init_kernel(const float* __restrict__ x, u64* __restrict__ xp,
            const float* __restrict__ c1v, const float* __restrict__ c1g,
            const float* __restrict__ c2v, const float* __restrict__ c2g,
            const float* __restrict__ c3v, const float* __restrict__ c3g,
            const float* __restrict__ d1v, const float* __restrict__ d1g,
            const float* __restrict__ d2v, const float* __restrict__ d2g)
{
    __shared__ unsigned int nsm[256 * 17];
    const int tid = threadIdx.x;

    if (blockIdx.x < 2048) {
        const float4* xg = (const float4*)x + (size_t)blockIdx.x * 4096;
        #pragma unroll
        for (int j = 0; j < 16; ++j) {
            float4 f = xg[j * 256 + tid];
            unsigned int v = (f.x > 0.5f ? 1u : 0u) | (f.y > 0.5f ? 2u : 0u)
                           | (f.z > 0.5f ? 4u : 0u) | (f.w > 0.5f ? 8u : 0u);
            int pl  = j * 16 + (tid >> 4);
            int nib = tid & 15;
            nsm[pl * 17 + nib] = v;
        }
        __syncthreads();
        u64 m = 0;
        #pragma unroll
        for (int k = 0; k < 16; ++k)
            m |= (u64)nsm[tid * 17 + k] << (4 * k);
        xp[(size_t)blockIdx.x * 256 + tid] = m;
        return;
    }

    int blk = blockIdx.x - 2048;
    const float* v; const float* g; float* w; int cols; int r; int d1 = 0;
    if (blk < 8)          { v = c1v; g = c1g; w = g_fbuf + W1_OFF; cols = 50;   r = blk; }
    else if (blk < 40)    { v = c2v; g = c2g; w = g_fbuf + W2_OFF; cols = 200;  r = blk - 8; }
    else if (blk < 104)   { v = c3v; g = c3g; w = g_fbuf + W3_OFF; cols = 800;  r = blk - 40; }
    else if (blk < 2160)  { v = d1v; g = d1g; w = 0;               cols = 256;  r = blk - 104; d1 = 1; }
    else                  { v = d2v; g = d2g; w = g_fbuf + W5_OFF; cols = 2056; r = blk - 2160; }

    float* red = (float*)nsm;
    float s = 0.0f;
    for (int i = tid; i < cols; i += 256) {
        float a = v[(size_t)r * cols + i];
        s += a * a;
    }
    red[tid] = s;
    __syncthreads();
    for (int off = 128; off > 0; off >>= 1) {
        if (tid < off) red[tid] += red[tid + off];
        __syncthreads();
    }
    float n = sqrtf(red[0]);
    float gr = g[r];
    if (d1) {
        if (tid == 0) g_fbuf[NRM1_OFF + r] = n;   // norm only
        return;
    }
    for (int i = tid; i < cols; i += 256)
        w[(size_t)r * cols + i] = gr * v[(size_t)r * cols + i] / n;
}

// ---------------------------------------------------------------------------
// dense1 transpose: w4t[i][r] = g_r * v[r][i] / n_r (same op order as the
// reference). Tiled 32x32 via smem: coalesced loads AND stores.
// Grid (65 r-tiles, 8 i-tiles) x 256 thr (32 tx x 8 ty).
// ---------------------------------------------------------------------------
__global__ void __launch_bounds__(256)
d1trans_kernel(const float* __restrict__ d1v, const float* __restrict__ d1g,
               float* __restrict__ w4t, const float* __restrict__ nrm1)
{
    __shared__ float tile[32][33];
    const int tx = threadIdx.x & 31, ty = threadIdx.x >> 5;
    const int r0 = blockIdx.x * 32, i0 = blockIdx.y * 32;

    #pragma unroll
    for (int k = 0; k < 4; ++k) {
        int rl = ty + k * 8;
        int r = r0 + rl;
        float val = 0.0f;
        if (r < 2056) {
            float gr = d1g[r];
            float n  = nrm1[r];
            val = gr * d1v[(size_t)r * 256 + i0 + tx] / n;
        }
        tile[rl][tx] = val;
    }
    __syncthreads();
    #pragma unroll
    for (int k = 0; k < 4; ++k) {
        int il = ty + k * 8;
        w4t[(size_t)(i0 + il) * W4T_STRIDE + r0 + tx] = tile[tx][il];
    }
}

// ---------------------------------------------------------------------------
// conv1: 2->8, in 128x128, out 32x32. Grid (16 b, 32 y, 2 xh) = 1024 blocks.
// 256 thr = 16 tq x 16 px; thread tile 8o x 4t = 16 FFMA2 per word.
// ---------------------------------------------------------------------------
__global__ void __launch_bounds__(256, 3)
conv1_kernel(const u64* __restrict__ xp, const float* __restrict__ wn,
             u64* __restrict__ sp)
{
    __shared__ u64 tile[2][5][65];                 // zero-padded halo
    __shared__ __align__(16) float wsm[400];       // [50 taps][8 o]
    __shared__ float zsm[128 * 65];                // 128 neurons

    const int b = blockIdx.x, y = blockIdx.y, xh = blockIdx.z;
    const int tid = threadIdx.x;
    const int tq = tid & 15, pxl = tid >> 4;

    for (int idx = tid; idx < 400; idx += 256)
        wsm[idx] = wn[(idx & 7) * 50 + (idx >> 3)];
    for (int idx = tid; idx < 650; idx += 256) {
        int c = idx / 325, rem = idx % 325;
        int r = rem / 65, col = rem % 65;
        int gy = 4 * y - 1 + r;
        int gx = xh * 64 - 1 + col;
        u64 v = 0ULL;
        if (gy >= 0 && gx >= 0)
            v = xp[(((size_t)b * 2 + c) << 14) + ((size_t)gy << 7) + gx];
        tile[c][r][col] = v;
    }
    __syncthreads();

    u64 acc[4][4];   // [opair][k(t)]
    #pragma unroll
    for (int j = 0; j < 4; ++j)
        #pragma unroll
        for (int k = 0; k < 4; ++k) acc[j][k] = 0ULL;

    #pragma unroll
    for (int c = 0; c < 2; ++c) {
        #pragma unroll 1
        for (int ky = 0; ky < 5; ++ky) {
            #pragma unroll
            for (int kx = 0; kx < 5; ++kx) {
                u64 word = tile[c][ky][pxl * 4 + kx];
                unsigned int lo = (unsigned int)word;
                unsigned int hi = (unsigned int)(word >> 32);
                u64 fd[4];
                fd[0] = bit2f2(lo, tq);
                fd[1] = bit2f2(lo, tq + 16);
                fd[2] = bit2f2(hi, tq);
                fd[3] = bit2f2(hi, tq + 16);
                const ulonglong2* wp =
                    (const ulonglong2*)(wsm + (c * 25 + ky * 5 + kx) * 8);
                ulonglong2 wA = wp[0];
                ulonglong2 wB = wp[1];
                u64 wpair[4] = {wA.x, wA.y, wB.x, wB.y};
                #pragma unroll
                for (int k = 0; k < 4; ++k)
                    #pragma unroll
                    for (int j = 0; j < 4; ++j)
                        ffma2(acc[j][k], wpair[j], fd[k]);
            }
        }
    }

    #pragma unroll
    for (int j = 0; j < 4; ++j)
        #pragma unroll
        for (int k = 0; k < 4; ++k) {
            float lo, hi;
            unpack2(acc[j][k], lo, hi);
            zsm[((2 * j)     * 16 + pxl) * 65 + tq + 16 * k] = lo;
            zsm[((2 * j + 1) * 16 + pxl) * 65 + tq + 16 * k] = hi;
        }
    __syncthreads();

    if (tid < 128) {   // CUBA: neuron = (o, pxl)
        int o = tid >> 4, p = tid & 15;
        float cc = 0.0f, vv = 0.0f;
        u64 m = 0;
        #pragma unroll 1
        for (int tt = 0; tt < 64; ++tt) {
            float z = zsm[tid * 65 + tt];
            cc = 0.7f * cc + z;
            vv = 0.75f * vv + cc;
            if (vv >= 1.0f) { m |= (1ULL << tt); vv = 0.0f; }
        }
        sp[(((size_t)b * 8 + o) * 32 + y) * 32 + xh * 16 + p] = m;
    }
}

// ---------------------------------------------------------------------------
// conv2: 8->32, in 32x32, out 8x8. Grid (16 b, 8 yq, 8 og of 4o) = 1024
// blocks x 128 thr. 16 tq x 8 px; thread tile 4o x 4t = 8 FFMA2 per word.
// ---------------------------------------------------------------------------
__global__ void __launch_bounds__(128, 7)
conv2_kernel(const u64* __restrict__ s1, const float* __restrict__ wn,
             u64* __restrict__ sp)
{
    __shared__ u64 tile[8][5][33];                 // zero-padded halo
    __shared__ __align__(16) float wsm[800];       // [200 taps][4 o]
    __shared__ float zsm[32 * 65];                 // 32 neurons

    const int b = blockIdx.x, yq = blockIdx.y, og = blockIdx.z;
    const int tid = threadIdx.x;
    const int tq = tid & 15, px = tid >> 4;        // px = output x, 0..7

    for (int idx = tid; idx < 800; idx += 128)
        wsm[idx] = wn[(og * 4 + (idx & 3)) * 200 + (idx >> 2)];
    for (int idx = tid; idx < 1320; idx += 128) {
        int c = idx / 165, rem = idx % 165;
        int r = rem / 33, col = rem % 33;
        int gy = 4 * yq - 1 + r;
        int gx = col - 1;
        u64 v = 0ULL;
        if (gy >= 0 && gx >= 0)
            v = s1[(((size_t)b * 8 + c) << 10) + ((size_t)gy << 5) + gx];
        tile[c][r][col] = v;
    }
    __syncthreads();

    u64 acc[2][4];   // [opair][k(t)]
    #pragma unroll
    for (int j = 0; j < 2; ++j)
        #pragma unroll
        for (int k = 0; k < 4; ++k) acc[j][k] = 0ULL;

    #pragma unroll 1
    for (int c = 0; c < 8; ++c) {
        #pragma unroll 1
        for (int ky = 0; ky < 5; ++ky) {
            #pragma unroll
            for (int kx = 0; kx < 5; ++kx) {
                u64 word = tile[c][ky][px * 4 + kx];
                unsigned int lo = (unsigned int)word;
                unsigned int hi = (unsigned int)(word >> 32);
                u64 fd[4];
                fd[0] = bit2f2(lo, tq);
                fd[1] = bit2f2(lo, tq + 16);
                fd[2] = bit2f2(hi, tq);
                fd[3] = bit2f2(hi, tq + 16);
                ulonglong2 wA =
                    *(const ulonglong2*)(wsm + (c * 25 + ky * 5 + kx) * 4);
                #pragma unroll
                for (int k = 0; k < 4; ++k) {
                    ffma2(acc[0][k], wA.x, fd[k]);
                    ffma2(acc[1][k], wA.y, fd[k]);
                }
            }
        }
    }

    #pragma unroll
    for (int j = 0; j < 2; ++j)
        #pragma unroll
        for (int k = 0; k < 4; ++k) {
            float lo, hi;
            unpack2(acc[j][k], lo, hi);
            zsm[((2 * j)     * 8 + px) * 65 + tq + 16 * k] = lo;
            zsm[((2 * j + 1) * 8 + px) * 65 + tq + 16 * k] = hi;
        }
    __syncthreads();

    if (tid < 32) {   // CUBA: neuron = (o_local, px)
        int o_loc = tid >> 3, p = tid & 7;
        float cc = 0.0f, vv = 0.0f;
        u64 m = 0;
        #pragma unroll 1
        for (int tt = 0; tt < 64; ++tt) {
            float z = zsm[tid * 65 + tt];
            cc = 0.7f * cc + z;
            vv = 0.75f * vv + cc;
            if (vv >= 1.0f) { m |= (1ULL << tt); vv = 0.0f; }
        }
        sp[(((size_t)b * 32 + og * 4 + o_loc) * 8 + yq) * 8 + p] = m;
    }
}

// ---------------------------------------------------------------------------
// conv3: 32->64, in 8x8, out 2x2. Grid (16 b, 8 og of 8 o) = 128 blocks
// x 1024 thr: 64t x 4pos x 4 csub (round-9 config, best measured).
// ---------------------------------------------------------------------------
__global__ void __launch_bounds__(1024, 1)
conv3_kernel(const u64* __restrict__ s2, const float* __restrict__ wn,
             u64* __restrict__ sp)
{
    extern __shared__ __align__(16) char sm3[];
    uint2* tile  = (uint2*)sm3;                     // 2048 u64 = 16 KB
    float* wsm   = (float*)(sm3 + 16384);           // 6400 f = 25.6 KB
    float* zpart = (float*)(sm3 + 16384 + 25600);   // 4*32*65 f

    const int b = blockIdx.x, og = blockIdx.y;
    const int tid = threadIdx.x;
    const int t = tid & 63, pq = (tid >> 6) & 3, csub = tid >> 8;
    const int y = pq >> 1, x = pq & 1;
    const bool hi_t = t >= 32;
    const unsigned int mb_t = t & 31;

    for (int idx = tid; idx < 6400; idx += 1024)
        wsm[idx] = wn[(og * 8 + (idx & 7)) * 800 + (idx >> 3)];
    {
        const uint2* src = (const uint2*)(s2 + (size_t)b * 2048);
        for (int idx = tid; idx < 2048; idx += 1024)
            tile[idx] = src[idx];
    }
    __syncthreads();

    u64 acc[4] = {0ULL, 0ULL, 0ULL, 0ULL};

    #pragma unroll 1
    for (int c = csub * 8; c < csub * 8 + 8; ++c) {
        #pragma unroll 1
        for (int ky = 0; ky < 5; ++ky) {
            int iy = 4 * y - 1 + ky;
            if (iy < 0) continue;
            #pragma unroll
            for (int kx = 0; kx < 5; ++kx) {
                int ix = 4 * x - 1 + kx;
                uint2 w2 = make_uint2(0u, 0u);
                if (ix >= 0) w2 = tile[c * 64 + iy * 8 + ix];
                unsigned int half = hi_t ? w2.y : w2.x;
                u64 f = bit2f2(half, mb_t);
                const ulonglong2* wp =
                    (const ulonglong2*)(wsm + (c * 25 + ky * 5 + kx) * 8);
                ulonglong2 w01 = wp[0];
                ulonglong2 w23 = wp[1];
                ffma2(acc[0], w01.x, f);
                ffma2(acc[1], w01.y, f);
                ffma2(acc[2], w23.x, f);
                ffma2(acc[3], w23.y, f);
            }
        }
    }

    #pragma unroll
    for (int j = 0; j < 4; ++j) {
        float lo, hi;
        unpack2(acc[j], lo, hi);
        zpart[(csub * 32 + (2 * j)     * 4 + pq) * 65 + t] = lo;
        zpart[(csub * 32 + (2 * j + 1) * 4 + pq) * 65 + t] = hi;
    }
    __syncthreads();

    if (tid < 32) {   // CUBA: neuron = (o_local, pos)
        int o = tid >> 2, p = tid & 3;
        float cc = 0.0f, vv = 0.0f;
        u64 m = 0;
        #pragma unroll 1
        for (int tt = 0; tt < 64; ++tt) {
            float z = ((zpart[tid * 65 + tt] + zpart[(32 + tid) * 65 + tt])
                     + zpart[(64 + tid) * 65 + tt]) + zpart[(96 + tid) * 65 + tt];
            cc = 0.7f * cc + z;
            vv = 0.75f * vv + cc;
            if (vv >= 1.0f) { m |= (1ULL << tt); vv = 0.0f; }
        }
        sp[(size_t)b * 256 + (og * 8 + o) * 4 + p] = m;
    }
}

// ---------------------------------------------------------------------------
// dense1: 256->2056 + CUBA. Grid (16 b, 33 og of 64 o) = 528 blocks x 256
// thr: 32 tq x 8 oq; thread tile 8o (4 pairs) x 2t = 8 FFMA2 per word.
// Block-uniform zero-word skip.
// ---------------------------------------------------------------------------
__global__ void __launch_bounds__(256, 5)
dense1_cuba_kernel(const u64* __restrict__ s3,
                   const float* __restrict__ w4t,
                   u64* __restrict__ s4)
{
    __shared__ u64 words[256];
    __shared__ __align__(16) float wsm[64 * 64];   // [i][64 o]
    __shared__ float zsm[64 * 65];

    const int b = blockIdx.x, og = blockIdx.y;
    const int tid = threadIdx.x;
    const int tq = tid & 31, oq = tid >> 5;        // oq 0..7, 8 o each

    words[tid] = s3[b * 256 + tid];

    u64 acc[4][2];
    #pragma unroll
    for (int j = 0; j < 4; ++j) { acc[j][0] = 0ULL; acc[j][1] = 0ULL; }

    #pragma unroll 1
    for (int q = 0; q < 4; ++q) {
        __syncthreads();
        #pragma unroll
        for (int r = 0; r < 4; ++r) {
            int f4 = r * 256 + tid;
            int ii = f4 >> 4;
            int o4 = (f4 & 15) * 4;
            *(float4*)(wsm + ii * 64 + o4) =
                *(const float4*)(w4t + (size_t)(q * 64 + ii) * W4T_STRIDE + og * 64 + o4);
        }
        __syncthreads();

        #pragma unroll 2
        for (int ii = 0; ii < 64; ++ii) {
            u64 wd = words[q * 64 + ii];
            if (wd == 0ULL) continue;          // block-uniform, exact skip
            u64 f0 = bit2f2((unsigned int)wd, tq);
            u64 f1 = bit2f2((unsigned int)(wd >> 32), tq);
            const ulonglong2* wp = (const ulonglong2*)(wsm + ii * 64 + oq * 8);
            ulonglong2 w0 = wp[0], w1 = wp[1];
            u64 wpair[4] = {w0.x, w0.y, w1.x, w1.y};
            #pragma unroll
            for (int j = 0; j < 4; ++j) {
                ffma2(acc[j][0], wpair[j], f0);
                ffma2(acc[j][1], wpair[j], f1);
            }
        }
    }

    #pragma unroll
    for (int j = 0; j < 4; ++j)
        #pragma unroll
        for (int k = 0; k < 2; ++k) {
            float lo, hi;
            unpack2(acc[j][k], lo, hi);
            zsm[(oq * 8 + 2 * j)     * 65 + tq + 32 * k] = lo;
            zsm[(oq * 8 + 2 * j + 1) * 65 + tq + 32 * k] = hi;
        }
    __syncthreads();

    if (tid < 64) {
        int o_g = og * 64 + tid;
        float cc = 0.0f, vv = 0.0f;
        u64 m = 0;
        #pragma unroll 1
        for (int tt = 0; tt < 64; ++tt) {
            float z = zsm[tid * 65 + tt];
            cc = 0.7f * cc + z;
            vv = 0.75f * vv + cc;
            if (vv >= 1.0f) { m |= (1ULL << tt); vv = 0.0f; }
        }
        if (o_g < 2056) s4[b * 2056 + o_g] = m;
    }
}

// ---------------------------------------------------------------------------
// dense2 (2056->11) + final CUBA + float output. Grid (16 b, 11 o).
// ---------------------------------------------------------------------------
__global__ void __launch_bounds__(256)
dense2_out_kernel(const u64* __restrict__ s4, const float* __restrict__ w5,
                  float* __restrict__ out)
{
    __shared__ float part[4][64];
    __shared__ float zrow[64];
    __shared__ u64 spk;

    const int b = blockIdx.x, o = blockIdx.y;
    const int tid = threadIdx.x;
    const int t = tid & 63, q = tid >> 6;

    float s = 0.0f;
    const u64*   wp = s4 + b * 2056;
    const float* vp = w5 + (size_t)o * 2056;
    for (int i = q * 514; i < q * 514 + 514; ++i) {
        float wt = vp[i];
        if ((wp[i] >> t) & 1ULL) s += wt;
    }
    part[q][t] = s;
    __syncthreads();
    if (tid < 64)
        zrow[tid] = part[0][tid] + part[1][tid] + part[2][tid] + part[3][tid];
    __syncthreads();
    if (tid == 0) {
        float cc = 0.0f, vv = 0.0f;
        u64 m = 0;
        #pragma unroll 1
        for (int tt = 0; tt < 64; ++tt) {
            cc = 0.7f * cc + zrow[tt];
            vv = 0.75f * vv + cc;
            if (vv >= 1.0f) { m |= (1ULL << tt); vv = 0.0f; }
        }
        spk = m;
    }
    __syncthreads();
    if (tid < 64)
        out[((size_t)b * 11 + o) * 64 + tid] = (float)((spk >> tid) & 1ULL);
}

// ---------------------------------------------------------------------------
// launch
// ---------------------------------------------------------------------------
extern "C" void kernel_launch(void* const* d_in, const int* in_sizes, int n_in,
                              void* d_out, int out_size)
{
    const float* x   = (const float*)d_in[0];
    const float* c1v = (const float*)d_in[1];
    const float* c1g = (const float*)d_in[2];
    const float* c2v = (const float*)d_in[3];
    const float* c2g = (const float*)d_in[4];
    const float* c3v = (const float*)d_in[5];
    const float* c3g = (const float*)d_in[6];
    const float* d1v = (const float*)d_in[7];
    const float* d1g = (const float*)d_in[8];
    const float* d2v = (const float*)d_in[9];
    const float* d2g = (const float*)d_in[10];
    float* out = (float*)d_out;

    void* fp = nullptr; void* up = nullptr;
    cudaGetSymbolAddress(&fp, g_fbuf);
    cudaGetSymbolAddress(&up, g_ubuf);
    float* F = (float*)fp;
    u64*   U = (u64*)up;

    float* W1  = F + W1_OFF;
    float* W2  = F + W2_OFF;
    float* W3  = F + W3_OFF;
    float* W4T = F + W4T_OFF;
    float* W5  = F + W5_OFF;
    float* NRM1 = F + NRM1_OFF;
    u64* XP = U + XP_OFF;  u64* S1 = U + S1_OFF;  u64* S2 = U + S2_OFF;
    u64* S3 = U + S3_OFF;  u64* S4 = U + S4_OFF;

    const int SM3 = 16384 + 25600 + 4 * 32 * 65 * 4;   // 75264 bytes
    cudaFuncSetAttribute(conv3_kernel,
                         cudaFuncAttributeMaxDynamicSharedMemorySize, SM3);

    init_kernel<<<4219, 256>>>(x, XP, c1v, c1g, c2v, c2g, c3v, c3g,
                               d1v, d1g, d2v, d2g);
    d1trans_kernel<<<dim3(65, 8), 256>>>(d1v, d1g, W4T, NRM1);

    conv1_kernel<<<dim3(16, 32, 2), 256>>>(XP, W1, S1);
    conv2_kernel<<<dim3(16, 8, 8), 128>>>(S1, W2, S2);
    conv3_kernel<<<dim3(16, 8), 1024, SM3>>>(S2, W3, S3);

    dense1_cuba_kernel<<<dim3(16, 33), 256>>>(S3, W4T, S4);
    dense2_out_kernel<<<dim3(16, 11), 256>>>(S4, W5, out);
}